// round 8
// baseline (speedup 1.0000x reference)
#include <cuda_runtime.h>
#include <math.h>
#include <stdint.h>

#define NEL 32
#define NUP 16
#define NI  32
#define NL  16
#define NK  16
#define H1  128
#define H2  4
#define FLEN 392
#define GRID 128

// ---- device-global state (no allocation allowed) ----
__device__ float g_sh[2][NEL][H1];
__device__ float g_dh[2][NEL][NEL][H2];
__device__ float g_rN[NEL][NI];
__device__ float g_phi[NK][2][16][16];
__device__ float g_det[NK][2];
__device__ __align__(16) unsigned g_flag[GRID];   // per-block epoch words
__device__ unsigned g_flagd[32];                  // det-phase flags

// ---------------- barrier: per-block release-store + warp-parallel poll ----
__device__ __forceinline__ void flag_set(unsigned val) {
    __syncthreads();                 // all block work done & ordered
    if (threadIdx.x == 0)
        asm volatile("st.release.gpu.global.u32 [%0], %1;"
                     :: "l"(&g_flag[blockIdx.x]), "r"(val) : "memory");
}
__device__ __forceinline__ void flag_wait_all(unsigned tgt) {
    if (threadIdx.x < 32) {
        const unsigned* p = &g_flag[threadIdx.x * 4];
        unsigned a, bb, cc, dd;
        for (;;) {
            asm volatile("ld.volatile.global.v4.u32 {%0,%1,%2,%3}, [%4];"
                         : "=r"(a), "=r"(bb), "=r"(cc), "=r"(dd) : "l"(p));
            bool ok = (a >= tgt) & (bb >= tgt) & (cc >= tgt) & (dd >= tgt);
            if (__all_sync(0xffffffffu, ok)) break;
        }
        asm volatile("fence.acq_rel.gpu;" ::: "memory");
    }
    __syncthreads();
}

// ---------------------------------------------------------------------------
// Preprocess + zero flags (every replay)
// ---------------------------------------------------------------------------
__global__ void pre_kernel(const float* __restrict__ ep,
                           const float* __restrict__ nuc) {
    int t = threadIdx.x;
    if (t < GRID) g_flag[t] = 0;
    if (t < 32)  g_flagd[t] = 0;
    for (int p = t; p < NEL * NI; p += blockDim.x) {
        int j = p >> 5, m = p & 31;
        float dx = ep[j * 3 + 0] - nuc[m * 3 + 0];
        float dy = ep[j * 3 + 1] - nuc[m * 3 + 1];
        float dz = ep[j * 3 + 2] - nuc[m * 3 + 2];
        float r  = sqrtf(dx * dx + dy * dy + dz * dz);
        g_sh[0][j][m * 3 + 0] = dx;
        g_sh[0][j][m * 3 + 1] = dy;
        g_sh[0][j][m * 3 + 2] = dz;
        g_sh[0][j][3 * NI + m] = r;
        g_rN[j][m] = r;
    }
    for (int p = t; p < NEL * NEL; p += blockDim.x) {
        int i = p >> 5, j = p & 31;
        float dx = ep[i * 3 + 0] - ep[j * 3 + 0];
        float dy = ep[i * 3 + 1] - ep[j * 3 + 1];
        float dz = ep[i * 3 + 2] - ep[j * 3 + 2];
        float r  = sqrtf(dx * dx + dy * dy + dz * dz);
        g_dh[0][i][j][0] = dx;
        g_dh[0][i][j][1] = dy;
        g_dh[0][i][j][2] = dz;
        g_dh[0][i][j][3] = r;
    }
}

// ---------------------------------------------------------------------------
// Fused persistent kernel. 128 blocks (n = b>>2, output quarter og = b&3).
// ---------------------------------------------------------------------------
__global__ void __launch_bounds__(256, 1) fused_kernel(
    const float* __restrict__ v,  const float* __restrict__ b,
    const float* __restrict__ w,  const float* __restrict__ c,
    const float* __restrict__ fw, const float* __restrict__ fb,
    const float* __restrict__ pi, const float* __restrict__ sigma,
    const float* __restrict__ omega, float* __restrict__ out)
{
    __shared__ float fsh[FLEN];
    __shared__ float part_s[8][33];
    __shared__ float A[16][17];
    __shared__ float fac[16];
    __shared__ int   pivs;
    __shared__ float dsh;

    const int t    = threadIdx.x;
    const int n    = blockIdx.x >> 2;
    const int og   = blockIdx.x & 3;
    const int c4   = t & 7;
    const int fs   = t >> 3;
    const int lane = t & 31, wrp = t >> 5;

#pragma unroll 1
    for (int l = 0; l < NL; l++) {
        // ---- prefetch weights (fly during the barrier spin) ----
        const float* vp = v + (((size_t)l * NEL + n) * FLEN) * H1 + og * 32 + c4 * 4;
        float4 wr[13];
#pragma unroll
        for (int i = 0; i < 12; i++)
            wr[i] = *reinterpret_cast<const float4*>(vp + (size_t)(fs + 32 * i) * H1);
        if (fs < 8)
            wr[12] = *reinterpret_cast<const float4*>(vp + (size_t)(fs + 384) * H1);

        float bias_r = 0.f;
        if (t < 32)
            bias_r = b[((size_t)l * NEL + n) * H1 + og * 32 + t];

        float4 dw0, dw1, dw2, dw3, dc4;
        const int dj = og * 8 + t;
        const bool do_d = (t < 8) && (l < NL - 1);
        if (do_d) {
            const float* wp = w + ((size_t)(l * NEL + n) * NEL + dj) * 16;
            dw0 = *reinterpret_cast<const float4*>(wp);
            dw1 = *reinterpret_cast<const float4*>(wp + 4);
            dw2 = *reinterpret_cast<const float4*>(wp + 8);
            dw3 = *reinterpret_cast<const float4*>(wp + 12);
            dc4 = *reinterpret_cast<const float4*>(
                c + ((size_t)(l * NEL + n) * NEL + dj) * 4);
        }

        // ---- wait for previous layer (all 128 flags >= l) ----
        if (l > 0) flag_wait_all((unsigned)l);
        const int cur = l & 1, nxt = cur ^ 1;

        // ---- feature vector ----
        if (t < H1) {
            float s = 0.f;
#pragma unroll
            for (int r = 0; r < NUP; r++) s += __ldcg(&g_sh[cur][r][t]);
            fsh[H1 + t] = s * (1.0f / 16);
            fsh[t] = __ldcg(&g_sh[cur][n][t]);
        } else {
            int o = t - H1;
            float s = 0.f;
#pragma unroll
            for (int r = NUP; r < NEL; r++) s += __ldcg(&g_sh[cur][r][o]);
            fsh[2 * H1 + o] = s * (1.0f / 16);
        }
        if (t < 8) {
            int d  = t & 3;
            int j0 = (t < 4) ? 0 : 16;
            float s = 0.f;
#pragma unroll
            for (int jj = 0; jj < 16; jj++) s += __ldcg(&g_dh[cur][n][j0 + jj][d]);
            fsh[3 * H1 + (t < 4 ? 0 : 4) + d] = s * (1.0f / 16);
        }
        __syncthreads();

        // ---- matvec ----
        float4 acc = make_float4(0.f, 0.f, 0.f, 0.f);
#pragma unroll
        for (int i = 0; i < 12; i++) {
            float s = fsh[fs + 32 * i];
            acc.x += s * wr[i].x; acc.y += s * wr[i].y;
            acc.z += s * wr[i].z; acc.w += s * wr[i].w;
        }
        if (fs < 8) {
            float s = fsh[fs + 384];
            acc.x += s * wr[12].x; acc.y += s * wr[12].y;
            acc.z += s * wr[12].z; acc.w += s * wr[12].w;
        }

        // ---- double stream (overlaps reduce) ----
        float4 od;
        if (do_d) {
            float4 d4 = __ldcg(reinterpret_cast<const float4*>(&g_dh[cur][n][dj][0]));
            float o0 = d4.x * dw0.x + d4.y * dw1.x + d4.z * dw2.x + d4.w * dw3.x;
            float o1 = d4.x * dw0.y + d4.y * dw1.y + d4.z * dw2.y + d4.w * dw3.y;
            float o2 = d4.x * dw0.z + d4.y * dw1.z + d4.z * dw2.z + d4.w * dw3.z;
            float o3 = d4.x * dw0.w + d4.y * dw1.w + d4.z * dw2.w + d4.w * dw3.w;
            od.x = tanhf(o0 + dc4.x) + d4.x;
            od.y = tanhf(o1 + dc4.y) + d4.y;
            od.z = tanhf(o2 + dc4.z) + d4.z;
            od.w = tanhf(o3 + dc4.w) + d4.w;
        }

        // ---- reduce ----
#pragma unroll
        for (int off = 16; off >= 8; off >>= 1) {
            acc.x += __shfl_down_sync(0xffffffffu, acc.x, off);
            acc.y += __shfl_down_sync(0xffffffffu, acc.y, off);
            acc.z += __shfl_down_sync(0xffffffffu, acc.z, off);
            acc.w += __shfl_down_sync(0xffffffffu, acc.w, off);
        }
        if (lane < 8) {
            part_s[wrp][lane * 4 + 0] = acc.x;
            part_s[wrp][lane * 4 + 1] = acc.y;
            part_s[wrp][lane * 4 + 2] = acc.z;
            part_s[wrp][lane * 4 + 3] = acc.w;
        }
        __syncthreads();

        // ---- tail: 32 threads, one output column each ----
        if (t < 32) {
            float a = part_s[0][t];
#pragma unroll
            for (int ww = 1; ww < 8; ww++) a += part_s[ww][t];
            int o = og * 32 + t;
            float val = tanhf(a + bias_r) + fsh[o];
            __stcg(&g_sh[nxt][n][o], val);
        }
        if (do_d)
            __stcg(reinterpret_cast<float4*>(&g_dh[nxt][n][dj][0]), od);

        flag_set((unsigned)(l + 1));
    }

    // ================= phi (diagonal 16x16 blocks only) =================
    flag_wait_all((unsigned)NL);
    {
        const int k    = blockIdx.x >> 3;
        const int i    = (blockIdx.x & 7) * 4 + (t >> 6);
        const int spin = i >> 4;
        const int tl   = t & 63;
        const int jl   = tl >> 2, s = tl & 3;
        const int j    = spin * 16 + jl;
        const float* fwp = fw + (size_t)(k * NEL + i) * H1;
        float dot = 0.f;
#pragma unroll
        for (int q = 0; q < 32; q++)
            dot += fwp[s + 4 * q] * __ldcg(&g_sh[0][j][s + 4 * q]);
        const float* pip = pi    + (size_t)(k * NEL + i) * NI;
        const float* sgp = sigma + (size_t)(k * NEL + i) * NI;
        float env = 0.f;
#pragma unroll
        for (int q = 0; q < 8; q++) {
            int m = s * 8 + q;
            env += pip[m] * __expf(-fabsf(sgp[m]) * g_rN[j][m]);
        }
        dot += __shfl_down_sync(0xffffffffu, dot, 2, 4);
        dot += __shfl_down_sync(0xffffffffu, dot, 1, 4);
        env += __shfl_down_sync(0xffffffffu, env, 2, 4);
        env += __shfl_down_sync(0xffffffffu, env, 1, 4);
        if (s == 0)
            __stcg(&g_phi[k][spin][i & 15][jl], (dot + fb[k * NEL + i]) * env);
    }
    flag_set((unsigned)(NL + 1));

    // ================= determinants (blocks 0..31) =================
    if (blockIdx.x < 32) {
        flag_wait_all((unsigned)(NL + 1));
        const int k = blockIdx.x >> 1, spin = blockIdx.x & 1;
        const int r = t >> 4, cc = t & 15;
        A[r][cc] = __ldcg(&g_phi[k][spin][r][cc]);
        if (t == 0) dsh = 1.0f;
        __syncthreads();
        for (int p = 0; p < 16; p++) {
            if (t == 0) {
                int best = p;
                float bv = fabsf(A[p][p]);
                for (int rr = p + 1; rr < 16; rr++) {
                    float v2 = fabsf(A[rr][p]);
                    if (v2 > bv) { bv = v2; best = rr; }
                }
                pivs = best;
                if (best != p) dsh = -dsh;
            }
            __syncthreads();
            int piv = pivs;
            if (piv != p && t < 16) {
                float tmp = A[p][t]; A[p][t] = A[piv][t]; A[piv][t] = tmp;
            }
            __syncthreads();
            if (t < 16 && t > p) fac[t] = A[t][p] / A[p][p];
            if (t == 0) dsh *= A[p][p];
            __syncthreads();
            if (r > p && cc > p) A[r][cc] -= fac[r] * A[p][cc];
            __syncthreads();
        }
        if (t == 0) __stcg(&g_det[k][spin], dsh);
        __syncthreads();
        if (t == 0)
            asm volatile("st.release.gpu.global.u32 [%0], %1;"
                         :: "l"(&g_flagd[blockIdx.x]), "r"(1u) : "memory");
    }

    // ================= final reduction (block 0) =================
    if (blockIdx.x == 0) {
        if (t < 32) {
            unsigned vflag;
            do {
                asm volatile("ld.volatile.global.u32 %0, [%1];"
                             : "=r"(vflag) : "l"(&g_flagd[t]));
            } while (!__all_sync(0xffffffffu, vflag >= 1u));
            asm volatile("fence.acq_rel.gpu;" ::: "memory");
            float vv = (t < NK) ? omega[t] * __ldcg(&g_det[t][0]) * __ldcg(&g_det[t][1])
                                : 0.0f;
#pragma unroll
            for (int off = 16; off; off >>= 1)
                vv += __shfl_down_sync(0xffffffffu, vv, off);
            if (t == 0) out[0] = vv;
        }
    }
}

extern "C" void kernel_launch(void* const* d_in, const int* in_sizes, int n_in,
                              void* d_out, int out_size) {
    const float* ep    = (const float*)d_in[0];
    const float* nuc   = (const float*)d_in[1];
    const float* v     = (const float*)d_in[2];
    const float* b     = (const float*)d_in[3];
    const float* w     = (const float*)d_in[4];
    const float* c     = (const float*)d_in[5];
    const float* fw    = (const float*)d_in[6];
    const float* fb    = (const float*)d_in[7];
    const float* pi    = (const float*)d_in[8];
    const float* sigma = (const float*)d_in[9];
    const float* omega = (const float*)d_in[10];

    pre_kernel<<<1, 256>>>(ep, nuc);
    fused_kernel<<<GRID, 256>>>(v, b, w, c, fw, fb, pi, sigma, omega,
                                (float*)d_out);
}

// round 9
// speedup vs baseline: 1.6844x; 1.6844x over previous
#include <cuda_runtime.h>
#include <math.h>
#include <stdint.h>

#define NEL 32
#define NUP 16
#define NI  32
#define NL  16
#define NK  16
#define H1  128
#define H2  4
#define FLEN 392
#define GRID 128

// ---- device-global state (no allocation allowed) ----
__device__ float g_sh[2][NEL][H1];
__device__ float g_dh[2][NEL][NEL][H2];
__device__ float g_rN[NEL][NI];
__device__ float g_phi[NK][2][16][16];
__device__ float g_det[NK][2];
__device__ unsigned g_bar[NL + 2];

// ---------------- R2's barrier, verbatim: RED arrive + single-line poll ----
__device__ __forceinline__ unsigned ld_acq(const unsigned* p) {
    unsigned v;
    asm volatile("ld.acquire.gpu.global.u32 %0, [%1];" : "=r"(v) : "l"(p) : "memory");
    return v;
}
__device__ __forceinline__ void red_rel_add1(unsigned* p) {
    asm volatile("red.release.gpu.global.add.u32 [%0], 1;" :: "l"(p) : "memory");
}
__device__ __forceinline__ void bar_arrive(int idx) {
    __syncthreads();
    if (threadIdx.x == 0) red_rel_add1(&g_bar[idx]);
}
__device__ __forceinline__ void bar_wait(int idx, unsigned target) {
    if (threadIdx.x == 0) {
        while (ld_acq(&g_bar[idx]) < target) { }
    }
    __syncthreads();
}

// ---------------------------------------------------------------------------
// Preprocess + zero barrier counters (every replay)
// ---------------------------------------------------------------------------
__global__ void pre_kernel(const float* __restrict__ ep,
                           const float* __restrict__ nuc) {
    int t = threadIdx.x;
    if (t < NL + 2) g_bar[t] = 0;
    for (int p = t; p < NEL * NI; p += blockDim.x) {
        int j = p >> 5, m = p & 31;
        float dx = ep[j * 3 + 0] - nuc[m * 3 + 0];
        float dy = ep[j * 3 + 1] - nuc[m * 3 + 1];
        float dz = ep[j * 3 + 2] - nuc[m * 3 + 2];
        float r  = sqrtf(dx * dx + dy * dy + dz * dz);
        g_sh[0][j][m * 3 + 0] = dx;
        g_sh[0][j][m * 3 + 1] = dy;
        g_sh[0][j][m * 3 + 2] = dz;
        g_sh[0][j][3 * NI + m] = r;
        g_rN[j][m] = r;
    }
    for (int p = t; p < NEL * NEL; p += blockDim.x) {
        int i = p >> 5, j = p & 31;
        float dx = ep[i * 3 + 0] - ep[j * 3 + 0];
        float dy = ep[i * 3 + 1] - ep[j * 3 + 1];
        float dz = ep[i * 3 + 2] - ep[j * 3 + 2];
        float r  = sqrtf(dx * dx + dy * dy + dz * dz);
        g_dh[0][i][j][0] = dx;
        g_dh[0][i][j][1] = dy;
        g_dh[0][i][j][2] = dz;
        g_dh[0][i][j][3] = r;
    }
}

// ---------------------------------------------------------------------------
// Fused persistent kernel. 128 blocks (n = b>>2, output quarter og = b&3).
// Single-buffer pipelining: layer l+1's loads issue right after layer l's
// matvec/dstream consume the registers, hiding them under reduce+sync+fsh.
// ---------------------------------------------------------------------------
__global__ void __launch_bounds__(256, 1) fused_kernel(
    const float* __restrict__ v,  const float* __restrict__ b,
    const float* __restrict__ w,  const float* __restrict__ c,
    const float* __restrict__ fw, const float* __restrict__ fb,
    const float* __restrict__ pi, const float* __restrict__ sigma,
    const float* __restrict__ omega, float* __restrict__ out)
{
    __shared__ float fsh[FLEN];
    __shared__ float part_s[8][33];
    __shared__ float A[16][17];
    __shared__ float fac[16];
    __shared__ int   pivs;
    __shared__ float dsh;

    const int t    = threadIdx.x;
    const int n    = blockIdx.x >> 2;
    const int og   = blockIdx.x & 3;
    const int c4   = t & 7;
    const int fs   = t >> 3;
    const int lane = t & 31, wrp = t >> 5;
    const int dj   = og * 8 + t;          // double-stream pair col (t<8)

    float4 wr[13];
    float4 dw0, dw1, dw2, dw3, dc4;
    float  bias_cur, bias_nxt;

    // ---- prologue: load layer 0's operands ----
    {
        const float* vp = v + ((size_t)n * FLEN) * H1 + og * 32 + c4 * 4;
#pragma unroll
        for (int i = 0; i < 12; i++)
            wr[i] = *reinterpret_cast<const float4*>(vp + (size_t)(fs + 32 * i) * H1);
        if (fs < 8)
            wr[12] = *reinterpret_cast<const float4*>(vp + (size_t)(fs + 384) * H1);
        if (t < 32) bias_cur = b[(size_t)n * H1 + og * 32 + t];
        if (t < 8) {
            const float* wp = w + ((size_t)n * NEL + dj) * 16;
            dw0 = *reinterpret_cast<const float4*>(wp);
            dw1 = *reinterpret_cast<const float4*>(wp + 4);
            dw2 = *reinterpret_cast<const float4*>(wp + 8);
            dw3 = *reinterpret_cast<const float4*>(wp + 12);
            dc4 = *reinterpret_cast<const float4*>(c + ((size_t)n * NEL + dj) * 4);
        }
    }

#pragma unroll 1
    for (int l = 0; l < NL; l++) {
        // ---- wait for previous layer ----
        if (l > 0) bar_wait(l - 1, GRID);
        const int cur = l & 1, nxt = cur ^ 1;

        // ---- feature vector ----
        if (t < H1) {
            float s = 0.f;
#pragma unroll
            for (int r = 0; r < NUP; r++) s += __ldcg(&g_sh[cur][r][t]);
            fsh[H1 + t] = s * (1.0f / 16);
            fsh[t] = __ldcg(&g_sh[cur][n][t]);
        } else {
            int o = t - H1;
            float s = 0.f;
#pragma unroll
            for (int r = NUP; r < NEL; r++) s += __ldcg(&g_sh[cur][r][o]);
            fsh[2 * H1 + o] = s * (1.0f / 16);
        }
        if (t < 8) {
            int d  = t & 3;
            int j0 = (t < 4) ? 0 : 16;
            float s = 0.f;
#pragma unroll
            for (int jj = 0; jj < 16; jj++) s += __ldcg(&g_dh[cur][n][j0 + jj][d]);
            fsh[3 * H1 + (t < 4 ? 0 : 4) + d] = s * (1.0f / 16);
        }
        __syncthreads();

        // ---- matvec (consumes wr) ----
        float4 acc = make_float4(0.f, 0.f, 0.f, 0.f);
#pragma unroll
        for (int i = 0; i < 12; i++) {
            float s = fsh[fs + 32 * i];
            acc.x += s * wr[i].x; acc.y += s * wr[i].y;
            acc.z += s * wr[i].z; acc.w += s * wr[i].w;
        }
        if (fs < 8) {
            float s = fsh[fs + 384];
            acc.x += s * wr[12].x; acc.y += s * wr[12].y;
            acc.z += s * wr[12].z; acc.w += s * wr[12].w;
        }

        // ---- double stream compute (consumes dw) ----
        float4 od;
        const bool do_d = (t < 8) && (l < NL - 1);
        if (do_d) {
            float4 d4 = __ldcg(reinterpret_cast<const float4*>(&g_dh[cur][n][dj][0]));
            float o0 = d4.x * dw0.x + d4.y * dw1.x + d4.z * dw2.x + d4.w * dw3.x;
            float o1 = d4.x * dw0.y + d4.y * dw1.y + d4.z * dw2.y + d4.w * dw3.y;
            float o2 = d4.x * dw0.z + d4.y * dw1.z + d4.z * dw2.z + d4.w * dw3.z;
            float o3 = d4.x * dw0.w + d4.y * dw1.w + d4.z * dw2.w + d4.w * dw3.w;
            od.x = tanhf(o0 + dc4.x) + d4.x;
            od.y = tanhf(o1 + dc4.y) + d4.y;
            od.z = tanhf(o2 + dc4.z) + d4.z;
            od.w = tanhf(o3 + dc4.w) + d4.w;
        }

        // ---- issue layer l+1 loads into the SAME registers (WAR via scoreboard)
        if (l + 1 < NL) {
            const int ln = l + 1;
            const float* vp = v + (((size_t)ln * NEL + n) * FLEN) * H1 + og * 32 + c4 * 4;
#pragma unroll
            for (int i = 0; i < 12; i++)
                wr[i] = *reinterpret_cast<const float4*>(vp + (size_t)(fs + 32 * i) * H1);
            if (fs < 8)
                wr[12] = *reinterpret_cast<const float4*>(vp + (size_t)(fs + 384) * H1);
            if (t < 32) bias_nxt = b[((size_t)ln * NEL + n) * H1 + og * 32 + t];
            if (t < 8 && ln < NL - 1) {
                const float* wp = w + ((size_t)(ln * NEL + n) * NEL + dj) * 16;
                dw0 = *reinterpret_cast<const float4*>(wp);
                dw1 = *reinterpret_cast<const float4*>(wp + 4);
                dw2 = *reinterpret_cast<const float4*>(wp + 8);
                dw3 = *reinterpret_cast<const float4*>(wp + 12);
                dc4 = *reinterpret_cast<const float4*>(
                    c + ((size_t)(ln * NEL + n) * NEL + dj) * 4);
            }
        }

        // ---- reduce ----
#pragma unroll
        for (int off = 16; off >= 8; off >>= 1) {
            acc.x += __shfl_down_sync(0xffffffffu, acc.x, off);
            acc.y += __shfl_down_sync(0xffffffffu, acc.y, off);
            acc.z += __shfl_down_sync(0xffffffffu, acc.z, off);
            acc.w += __shfl_down_sync(0xffffffffu, acc.w, off);
        }
        if (lane < 8) {
            part_s[wrp][lane * 4 + 0] = acc.x;
            part_s[wrp][lane * 4 + 1] = acc.y;
            part_s[wrp][lane * 4 + 2] = acc.z;
            part_s[wrp][lane * 4 + 3] = acc.w;
        }
        __syncthreads();

        // ---- tail: 32 threads, one output column each ----
        if (t < 32) {
            float a = part_s[0][t];
#pragma unroll
            for (int ww = 1; ww < 8; ww++) a += part_s[ww][t];
            int o = og * 32 + t;
            float val = tanhf(a + bias_cur) + fsh[o];
            __stcg(&g_sh[nxt][n][o], val);
            bias_cur = bias_nxt;
        }
        if (do_d)
            __stcg(reinterpret_cast<float4*>(&g_dh[nxt][n][dj][0]), od);

        bar_arrive(l);
    }

    // ================= phi (diagonal 16x16 blocks only) =================
    bar_wait(NL - 1, GRID);
    {
        const int k    = blockIdx.x >> 3;
        const int i    = (blockIdx.x & 7) * 4 + (t >> 6);
        const int spin = i >> 4;
        const int tl   = t & 63;
        const int jl   = tl >> 2, s = tl & 3;
        const int j    = spin * 16 + jl;
        const float* fwp = fw + (size_t)(k * NEL + i) * H1;
        float dot = 0.f;
#pragma unroll
        for (int q = 0; q < 32; q++)
            dot += fwp[s + 4 * q] * __ldcg(&g_sh[0][j][s + 4 * q]);
        const float* pip = pi    + (size_t)(k * NEL + i) * NI;
        const float* sgp = sigma + (size_t)(k * NEL + i) * NI;
        float env = 0.f;
#pragma unroll
        for (int q = 0; q < 8; q++) {
            int m = s * 8 + q;
            env += pip[m] * __expf(-fabsf(sgp[m]) * g_rN[j][m]);
        }
        dot += __shfl_down_sync(0xffffffffu, dot, 2, 4);
        dot += __shfl_down_sync(0xffffffffu, dot, 1, 4);
        env += __shfl_down_sync(0xffffffffu, env, 2, 4);
        env += __shfl_down_sync(0xffffffffu, env, 1, 4);
        if (s == 0)
            __stcg(&g_phi[k][spin][i & 15][jl], (dot + fb[k * NEL + i]) * env);
    }
    bar_arrive(NL);

    // ================= determinants (blocks 0..31) =================
    if (blockIdx.x < 32) {
        bar_wait(NL, GRID);
        const int k = blockIdx.x >> 1, spin = blockIdx.x & 1;
        const int r = t >> 4, cc = t & 15;
        A[r][cc] = __ldcg(&g_phi[k][spin][r][cc]);
        if (t == 0) dsh = 1.0f;
        __syncthreads();
        for (int p = 0; p < 16; p++) {
            if (t == 0) {
                int best = p;
                float bv = fabsf(A[p][p]);
                for (int rr = p + 1; rr < 16; rr++) {
                    float v2 = fabsf(A[rr][p]);
                    if (v2 > bv) { bv = v2; best = rr; }
                }
                pivs = best;
                if (best != p) dsh = -dsh;
            }
            __syncthreads();
            int piv = pivs;
            if (piv != p && t < 16) {
                float tmp = A[p][t]; A[p][t] = A[piv][t]; A[piv][t] = tmp;
            }
            __syncthreads();
            if (t < 16 && t > p) fac[t] = A[t][p] / A[p][p];
            if (t == 0) dsh *= A[p][p];
            __syncthreads();
            if (r > p && cc > p) A[r][cc] -= fac[r] * A[p][cc];
            __syncthreads();
        }
        if (t == 0) __stcg(&g_det[k][spin], dsh);
        bar_arrive(NL + 1);
    }

    // ================= final reduction (block 0) =================
    if (blockIdx.x == 0) {
        bar_wait(NL + 1, 32);
        if (t < 32) {
            float vv = (t < NK) ? omega[t] * __ldcg(&g_det[t][0]) * __ldcg(&g_det[t][1])
                                : 0.0f;
#pragma unroll
            for (int off = 16; off; off >>= 1)
                vv += __shfl_down_sync(0xffffffffu, vv, off);
            if (t == 0) out[0] = vv;
        }
    }
}

extern "C" void kernel_launch(void* const* d_in, const int* in_sizes, int n_in,
                              void* d_out, int out_size) {
    const float* ep    = (const float*)d_in[0];
    const float* nuc   = (const float*)d_in[1];
    const float* v     = (const float*)d_in[2];
    const float* b     = (const float*)d_in[3];
    const float* w     = (const float*)d_in[4];
    const float* c     = (const float*)d_in[5];
    const float* fw    = (const float*)d_in[6];
    const float* fb    = (const float*)d_in[7];
    const float* pi    = (const float*)d_in[8];
    const float* sigma = (const float*)d_in[9];
    const float* omega = (const float*)d_in[10];

    pre_kernel<<<1, 256>>>(ep, nuc);
    fused_kernel<<<GRID, 256>>>(v, b, w, c, fw, fb, pi, sigma, omega,
                                (float*)d_out);
}

// round 11
// speedup vs baseline: 1.8420x; 1.0936x over previous
#include <cuda_runtime.h>
#include <math.h>
#include <stdint.h>

#define NEL 32
#define NUP 16
#define NI  32
#define NL  16
#define NK  16
#define H1  128
#define H2  4
#define FLEN 392
#define GRID 128

// ---- device-global state (no allocation allowed) ----
__device__ float g_sh[2][NEL][H1];
__device__ float g_rN[NEL][NI];
__device__ float g_phi[NK][2][16][16];
__device__ float g_det[NK][2];
__device__ unsigned g_bar[NL + 2];

// ---------------- R2's barrier, verbatim ----------------
__device__ __forceinline__ unsigned ld_acq(const unsigned* p) {
    unsigned v;
    asm volatile("ld.acquire.gpu.global.u32 %0, [%1];" : "=r"(v) : "l"(p) : "memory");
    return v;
}
__device__ __forceinline__ void red_rel_add1(unsigned* p) {
    asm volatile("red.release.gpu.global.add.u32 [%0], 1;" :: "l"(p) : "memory");
}
__device__ __forceinline__ void bar_arrive(int idx) {
    __syncthreads();
    if (threadIdx.x == 0) red_rel_add1(&g_bar[idx]);
}
__device__ __forceinline__ void bar_wait(int idx, unsigned target) {
    if (threadIdx.x == 0) {
        while (ld_acq(&g_bar[idx]) < target) { }
    }
    __syncthreads();
}

// ---------------- cluster / DSMEM helpers ----------------
__device__ __forceinline__ void cluster_arrive() {
    asm volatile("barrier.cluster.arrive.aligned;" ::: "memory");
}
__device__ __forceinline__ void cluster_wait() {
    asm volatile("barrier.cluster.wait.aligned;" ::: "memory");
}
__device__ __forceinline__ uint32_t mapa_addr(uint32_t saddr, int rank) {
    uint32_t r;
    asm("mapa.shared::cluster.u32 %0, %1, %2;" : "=r"(r) : "r"(saddr), "r"(rank));
    return r;
}
__device__ __forceinline__ void st_dsm(uint32_t saddr, float v) {
    asm volatile("st.shared::cluster.f32 [%0], %1;" :: "r"(saddr), "f"(v) : "memory");
}

// ---------------------------------------------------------------------------
// Preprocess: g_sh layer-0 + rN + zero barrier counters (every replay)
// ---------------------------------------------------------------------------
__global__ void pre_kernel(const float* __restrict__ ep,
                           const float* __restrict__ nuc) {
    int t = threadIdx.x;
    if (t < NL + 2) g_bar[t] = 0;
    for (int p = t; p < NEL * NI; p += blockDim.x) {
        int j = p >> 5, m = p & 31;
        float dx = ep[j * 3 + 0] - nuc[m * 3 + 0];
        float dy = ep[j * 3 + 1] - nuc[m * 3 + 1];
        float dz = ep[j * 3 + 2] - nuc[m * 3 + 2];
        float r  = sqrtf(dx * dx + dy * dy + dz * dz);
        g_sh[0][j][m * 3 + 0] = dx;
        g_sh[0][j][m * 3 + 1] = dy;
        g_sh[0][j][m * 3 + 2] = dz;
        g_sh[0][j][3 * NI + m] = r;
        g_rN[j][m] = r;
    }
}

// ---------------------------------------------------------------------------
// Fused persistent kernel. 128 blocks = 32 clusters of 4 (electron n = b>>2,
// output quarter og = b&3 = cluster rank). Local terms (own sh + dg) exchange
// via DSMEM and compute BEFORE the chip barrier; only mean terms wait on it.
// ---------------------------------------------------------------------------
__global__ void __launch_bounds__(256, 1) __cluster_dims__(4, 1, 1) fused_kernel(
    const float* __restrict__ ep, const float* __restrict__ nuc,
    const float* __restrict__ v,
    const float* __restrict__ b,  const float* __restrict__ w,
    const float* __restrict__ c,  const float* __restrict__ fw,
    const float* __restrict__ fb, const float* __restrict__ pi,
    const float* __restrict__ sigma, const float* __restrict__ omega,
    float* __restrict__ out)
{
    __shared__ float m_s[256];          // [g_up(128) | g_dn(128)]
    __shared__ float sh_loc[2][H1];     // full sh[n], double-buffered by parity
    __shared__ float pd[2][4][4];       // dh partial sums per og-rank
    __shared__ float dg_s[8];
    __shared__ float part_s[8][33];
    __shared__ float A[16][17];
    __shared__ float fac[16];
    __shared__ int   pivs;
    __shared__ float dsh;

    const int t    = threadIdx.x;
    const int n    = blockIdx.x >> 2;
    const int og   = blockIdx.x & 3;
    const int c4   = t & 7;
    const int fs   = t >> 3;
    const int lane = t & 31, wrp = t >> 5;
    const int dj   = og * 8 + t;        // this block's dh pair column (t<8)

    const uint32_t shloc_s = (uint32_t)__cvta_generic_to_shared(&sh_loc[0][0]);
    const uint32_t pd_s    = (uint32_t)__cvta_generic_to_shared(&pd[0][0][0]);

    // ---------------- prologue: local sh^0, dh^0 + partials ----------------
    if (t < H1) {
        float val;
        if (t < 96) {
            int m = t / 3, cp = t % 3;
            val = ep[n * 3 + cp] - nuc[m * 3 + cp];
        } else {
            int m = t - 96;
            float dx = ep[n * 3 + 0] - nuc[m * 3 + 0];
            float dy = ep[n * 3 + 1] - nuc[m * 3 + 1];
            float dz = ep[n * 3 + 2] - nuc[m * 3 + 2];
            val = sqrtf(dx * dx + dy * dy + dz * dz);
        }
        sh_loc[0][t] = val;
    }
    float4 d4;
    if (t < 8) {
        float dx = ep[n * 3 + 0] - ep[dj * 3 + 0];
        float dy = ep[n * 3 + 1] - ep[dj * 3 + 1];
        float dz = ep[n * 3 + 2] - ep[dj * 3 + 2];
        d4 = make_float4(dx, dy, dz, sqrtf(dx * dx + dy * dy + dz * dz));
        float4 s = d4;
        s.x += __shfl_down_sync(0xffu, s.x, 4, 8);
        s.y += __shfl_down_sync(0xffu, s.y, 4, 8);
        s.z += __shfl_down_sync(0xffu, s.z, 4, 8);
        s.w += __shfl_down_sync(0xffu, s.w, 4, 8);
        s.x += __shfl_down_sync(0xffu, s.x, 2, 8);
        s.y += __shfl_down_sync(0xffu, s.y, 2, 8);
        s.z += __shfl_down_sync(0xffu, s.z, 2, 8);
        s.w += __shfl_down_sync(0xffu, s.w, 2, 8);
        s.x += __shfl_down_sync(0xffu, s.x, 1, 8);
        s.y += __shfl_down_sync(0xffu, s.y, 1, 8);
        s.z += __shfl_down_sync(0xffu, s.z, 1, 8);
        s.w += __shfl_down_sync(0xffu, s.w, 1, 8);
        if (t == 0) {
            uint32_t base = pd_s + (0 * 4 + og) * 16;   // pd[0][og][0..3]
            for (int rk = 0; rk < 4; rk++) {
                uint32_t ra = mapa_addr(base, rk);
                st_dsm(ra + 0,  s.x);
                st_dsm(ra + 4,  s.y);
                st_dsm(ra + 8,  s.z);
                st_dsm(ra + 12, s.w);
            }
        }
    }
    cluster_arrive();

    float4 wr[13];
    float4 dw0, dw1, dw2, dw3, dc4;

#pragma unroll 1
    for (int l = 0; l < NL; l++) {
        const int p   = l & 1;          // sh_loc / pd buffer parity
        const int cur = l & 1, nxt = cur ^ 1;

        // ---- prefetch weights for this layer (fly during waits) ----
        {
            const float* vp = v + (((size_t)l * NEL + n) * FLEN) * H1 + og * 32 + c4 * 4;
#pragma unroll
            for (int i = 0; i < 12; i++)
                wr[i] = *reinterpret_cast<const float4*>(vp + (size_t)(fs + 32 * i) * H1);
            if (fs < 8)
                wr[12] = *reinterpret_cast<const float4*>(vp + (size_t)(fs + 384) * H1);
        }
        float bias_r = 0.f;
        if (t < 32) bias_r = b[((size_t)l * NEL + n) * H1 + og * 32 + t];
        const bool do_d = (t < 8) && (l < NL - 1);
        if (do_d) {
            const float* wp = w + ((size_t)(l * NEL + n) * NEL + dj) * 16;
            dw0 = *reinterpret_cast<const float4*>(wp);
            dw1 = *reinterpret_cast<const float4*>(wp + 4);
            dw2 = *reinterpret_cast<const float4*>(wp + 8);
            dw3 = *reinterpret_cast<const float4*>(wp + 12);
            dc4 = *reinterpret_cast<const float4*>(
                c + ((size_t)(l * NEL + n) * NEL + dj) * 4);
        }

        // ---- cluster-local data ready (sh_loc[p], pd[p]) ----
        cluster_wait();
        if (t < 8) {
            int d = t & 3;
            float a = (t < 4) ? (pd[p][0][d] + pd[p][1][d])
                              : (pd[p][2][d] + pd[p][3][d]);
            dg_s[t] = a * (1.0f / 16);
        }
        __syncthreads();

        // ---- LOCAL matvec part (rows 0..127 = own sh, 384..391 = dg) ----
        float4 acc = make_float4(0.f, 0.f, 0.f, 0.f);
#pragma unroll
        for (int i = 0; i < 4; i++) {
            float s = sh_loc[p][fs + 32 * i];
            acc.x += s * wr[i].x; acc.y += s * wr[i].y;
            acc.z += s * wr[i].z; acc.w += s * wr[i].w;
        }
        if (fs < 8) {
            float s = dg_s[fs];
            acc.x += s * wr[12].x; acc.y += s * wr[12].y;
            acc.z += s * wr[12].z; acc.w += s * wr[12].w;
        }

        // ---- dh update (local, register-resident) overlaps the chip wait ----
        float4 od;
        if (do_d) {
            float o0 = d4.x * dw0.x + d4.y * dw1.x + d4.z * dw2.x + d4.w * dw3.x;
            float o1 = d4.x * dw0.y + d4.y * dw1.y + d4.z * dw2.y + d4.w * dw3.y;
            float o2 = d4.x * dw0.z + d4.y * dw1.z + d4.z * dw2.z + d4.w * dw3.z;
            float o3 = d4.x * dw0.w + d4.y * dw1.w + d4.z * dw2.w + d4.w * dw3.w;
            od.x = tanhf(o0 + dc4.x) + d4.x;
            od.y = tanhf(o1 + dc4.y) + d4.y;
            od.z = tanhf(o2 + dc4.z) + d4.z;
            od.w = tanhf(o3 + dc4.w) + d4.w;
        }

        // ---- chip barrier: previous layer's activations visible ----
        if (l > 0) bar_wait(l - 1, GRID);

        // ---- mean gather (the only chip-dependent input) ----
        if (t < 128) {
            float s = 0.f;
#pragma unroll
            for (int r = 0; r < NUP; r++) s += __ldcg(&g_sh[cur][r][t]);
            m_s[t] = s * (1.0f / 16);
        } else {
            int o = t - 128;
            float s = 0.f;
#pragma unroll
            for (int r = NUP; r < NEL; r++) s += __ldcg(&g_sh[cur][r][o]);
            m_s[128 + o] = s * (1.0f / 16);
        }
        __syncthreads();

        // ---- MEAN matvec part (rows 128..383) ----
#pragma unroll
        for (int q = 0; q < 8; q++) {
            float s = m_s[fs + 32 * q];
            acc.x += s * wr[4 + q].x; acc.y += s * wr[4 + q].y;
            acc.z += s * wr[4 + q].z; acc.w += s * wr[4 + q].w;
        }

        // ---- reduce ----
#pragma unroll
        for (int off = 16; off >= 8; off >>= 1) {
            acc.x += __shfl_down_sync(0xffffffffu, acc.x, off);
            acc.y += __shfl_down_sync(0xffffffffu, acc.y, off);
            acc.z += __shfl_down_sync(0xffffffffu, acc.z, off);
            acc.w += __shfl_down_sync(0xffffffffu, acc.w, off);
        }
        if (lane < 8) {
            part_s[wrp][lane * 4 + 0] = acc.x;
            part_s[wrp][lane * 4 + 1] = acc.y;
            part_s[wrp][lane * 4 + 2] = acc.z;
            part_s[wrp][lane * 4 + 3] = acc.w;
        }
        __syncthreads();

        // ---- tail: 32 threads, one output column each ----
        if (t < 32) {
            float a = part_s[0][t];
#pragma unroll
            for (int ww = 1; ww < 8; ww++) a += part_s[ww][t];
            int o = og * 32 + t;
            float val = tanhf(a + bias_r) + sh_loc[p][o];
            __stcg(&g_sh[nxt][n][o], val);                       // for means + phi
            if (l < NL - 1) {                                     // DSMEM broadcast
                uint32_t base = shloc_s + ((p ^ 1) * H1 + o) * 4;
#pragma unroll
                for (int rk = 0; rk < 4; rk++)
                    st_dsm(mapa_addr(base, rk), val);
            }
        }

        // ---- dh partials for next layer ----
        if (do_d) {
            d4 = od;
            float4 s = d4;
            s.x += __shfl_down_sync(0xffu, s.x, 4, 8);
            s.y += __shfl_down_sync(0xffu, s.y, 4, 8);
            s.z += __shfl_down_sync(0xffu, s.z, 4, 8);
            s.w += __shfl_down_sync(0xffu, s.w, 4, 8);
            s.x += __shfl_down_sync(0xffu, s.x, 2, 8);
            s.y += __shfl_down_sync(0xffu, s.y, 2, 8);
            s.z += __shfl_down_sync(0xffu, s.z, 2, 8);
            s.w += __shfl_down_sync(0xffu, s.w, 2, 8);
            s.x += __shfl_down_sync(0xffu, s.x, 1, 8);
            s.y += __shfl_down_sync(0xffu, s.y, 1, 8);
            s.z += __shfl_down_sync(0xffu, s.z, 1, 8);
            s.w += __shfl_down_sync(0xffu, s.w, 1, 8);
            if (t == 0) {
                uint32_t base = pd_s + (((p ^ 1) * 4 + og) * 4) * 4;
                for (int rk = 0; rk < 4; rk++) {
                    uint32_t ra = mapa_addr(base, rk);
                    st_dsm(ra + 0,  s.x);
                    st_dsm(ra + 4,  s.y);
                    st_dsm(ra + 8,  s.z);
                    st_dsm(ra + 12, s.w);
                }
            }
        }
        if (l < NL - 1) cluster_arrive();
        bar_arrive(l);
    }

    // ================= phi (diagonal 16x16 blocks only) =================
    bar_wait(NL - 1, GRID);
    {
        const int k    = blockIdx.x >> 3;
        const int i    = (blockIdx.x & 7) * 4 + (t >> 6);
        const int spin = i >> 4;
        const int tl   = t & 63;
        const int jl   = tl >> 2, s = tl & 3;
        const int j    = spin * 16 + jl;
        const float* fwp = fw + (size_t)(k * NEL + i) * H1;
        float dot = 0.f;
#pragma unroll
        for (int q = 0; q < 32; q++)
            dot += fwp[s + 4 * q] * __ldcg(&g_sh[0][j][s + 4 * q]);
        const float* pip = pi    + (size_t)(k * NEL + i) * NI;
        const float* sgp = sigma + (size_t)(k * NEL + i) * NI;
        float env = 0.f;
#pragma unroll
        for (int q = 0; q < 8; q++) {
            int m = s * 8 + q;
            env += pip[m] * __expf(-fabsf(sgp[m]) * g_rN[j][m]);
        }
        dot += __shfl_down_sync(0xffffffffu, dot, 2, 4);
        dot += __shfl_down_sync(0xffffffffu, dot, 1, 4);
        env += __shfl_down_sync(0xffffffffu, env, 2, 4);
        env += __shfl_down_sync(0xffffffffu, env, 1, 4);
        if (s == 0)
            __stcg(&g_phi[k][spin][i & 15][jl], (dot + fb[k * NEL + i]) * env);
    }
    bar_arrive(NL);

    // ================= determinants (blocks 0..31) =================
    if (blockIdx.x < 32) {
        bar_wait(NL, GRID);
        const int k = blockIdx.x >> 1, spin = blockIdx.x & 1;
        const int r = t >> 4, cc = t & 15;
        A[r][cc] = __ldcg(&g_phi[k][spin][r][cc]);
        if (t == 0) dsh = 1.0f;
        __syncthreads();
        for (int pp = 0; pp < 16; pp++) {
            if (t == 0) {
                int best = pp;
                float bv = fabsf(A[pp][pp]);
                for (int rr = pp + 1; rr < 16; rr++) {
                    float v2 = fabsf(A[rr][pp]);
                    if (v2 > bv) { bv = v2; best = rr; }
                }
                pivs = best;
                if (best != pp) dsh = -dsh;
            }
            __syncthreads();
            int piv = pivs;
            if (piv != pp && t < 16) {
                float tmp = A[pp][t]; A[pp][t] = A[piv][t]; A[piv][t] = tmp;
            }
            __syncthreads();
            if (t < 16 && t > pp) fac[t] = A[t][pp] / A[pp][pp];
            if (t == 0) dsh *= A[pp][pp];
            __syncthreads();
            if (r > pp && cc > pp) A[r][cc] -= fac[r] * A[pp][cc];
            __syncthreads();
        }
        if (t == 0) __stcg(&g_det[k][spin], dsh);
        bar_arrive(NL + 1);
    }

    // ================= final reduction (block 0) =================
    if (blockIdx.x == 0) {
        bar_wait(NL + 1, 32);
        if (t < 32) {
            float vv = (t < NK) ? omega[t] * __ldcg(&g_det[t][0]) * __ldcg(&g_det[t][1])
                                : 0.0f;
#pragma unroll
            for (int off = 16; off; off >>= 1)
                vv += __shfl_down_sync(0xffffffffu, vv, off);
            if (t == 0) out[0] = vv;
        }
    }
}

extern "C" void kernel_launch(void* const* d_in, const int* in_sizes, int n_in,
                              void* d_out, int out_size) {
    const float* ep    = (const float*)d_in[0];
    const float* nuc   = (const float*)d_in[1];
    const float* v     = (const float*)d_in[2];
    const float* b     = (const float*)d_in[3];
    const float* w     = (const float*)d_in[4];
    const float* c     = (const float*)d_in[5];
    const float* fw    = (const float*)d_in[6];
    const float* fb    = (const float*)d_in[7];
    const float* pi    = (const float*)d_in[8];
    const float* sigma = (const float*)d_in[9];
    const float* omega = (const float*)d_in[10];

    pre_kernel<<<1, 256>>>(ep, nuc);
    fused_kernel<<<GRID, 256>>>(ep, nuc, v, b, w, c, fw, fb, pi, sigma, omega,
                                (float*)d_out);
}